// round 14
// baseline (speedup 1.0000x reference)
#include <cuda_runtime.h>
#include <stdint.h>

#define BN_EPS 1e-5f

namespace {
constexpr int Nn = 64, C = 256, H = 56, W = 56;
constexpr int PD = 58;             // padded dim
constexpr int WORDS = 8;           // channel words
constexpr int TB = 4;              // output rows per block
constexpr int TR = TB + 2;         // tile rows (with halo)
constexpr int TRPD = TR * PD;      // 348
constexpr int TILE_U2 = WORDS * TRPD;             // 2784 uint2
constexpr int ZC_OFF = TILE_U2 * 8;               // 22272 B
constexpr int SB_OFF = ZC_OFF + TRPD * 4;         // + 1392 -> 23664
constexpr int STG_OFF = SB_OFF + TB * W * 4;      // + 896 -> 24560
constexpr int DYN1 = STG_OFF;                     // conv1: 24560 B
constexpr int DYN2 = STG_OFF + C * 57 * 4;        // conv2: + 58368 -> 82928 B
}

// Packed (sign, nonzero) bitplanes, zero-padded borders. uint2 = (s, z).
__device__ uint2 g_p1[(size_t)Nn * PD * PD * WORDS];
__device__ uint2 g_p2[(size_t)Nn * PD * PD * WORDS];
__device__ uint32_t g_wb1[C * 72];   // [co][wd][tap]
__device__ uint32_t g_wb2[C * 72];
__device__ float g_sc1[C], g_sh1[C], g_sc2[C], g_sh2[C];

__device__ __forceinline__ void madacc1(int& a, int p) {  // a += p (fma pipe)
    asm("mad.lo.s32 %0, %1, 1, %0;" : "+r"(a) : "r"(p));
}
__device__ __forceinline__ int madn2(int acc, int d0) {   // d0 - 2*acc (fma pipe)
    int r;
    asm("mad.lo.s32 %0, %1, -2, %2;" : "=r"(r) : "r"(acc), "r"(d0));
    return r;
}

__global__ void k_zero() {
    size_t tot = (size_t)Nn * PD * PD * WORDS / 2;  // uint4 count
    size_t stride = (size_t)gridDim.x * blockDim.x;
    uint4 z = {0u, 0u, 0u, 0u};
    for (size_t i = blockIdx.x * (size_t)blockDim.x + threadIdx.x; i < tot; i += stride) {
        ((uint4*)g_p1)[i] = z;
        ((uint4*)g_p2)[i] = z;
    }
}

// grid (H, N), block (W=56, WORDS=8)
__global__ void k_pack_x(const float* __restrict__ x) {
    const int h = blockIdx.x, n = blockIdx.y;
    const int w = threadIdx.x, wd = threadIdx.y;
    const float* xp = x + (((size_t)n * C + wd * 32) * H + h) * W + w;
    uint32_t s = 0, z = 0;
#pragma unroll
    for (int ci = 0; ci < 32; ci++) {
        float v = xp[(size_t)ci * (H * W)];
        s |= (v > 0.f ? 1u : 0u) << ci;
        z |= (v != 0.f ? 1u : 0u) << ci;
    }
    g_p1[(((size_t)n * PD + (h + 1)) * PD + (w + 1)) * WORDS + wd] = make_uint2(s, z);
}

// grid C, block (WORDS=8, 9): layout [co][wd][tap]
__global__ void k_pack_w(const float* __restrict__ w, int which) {
    uint32_t* __restrict__ outw = which ? g_wb2 : g_wb1;
    const int co = blockIdx.x, wd = threadIdx.x, tap = threadIdx.y;
    uint32_t s = 0;
#pragma unroll
    for (int ci = 0; ci < 32; ci++)
        s |= (w[(((size_t)co * C) + wd * 32 + ci) * 9 + tap] > 0.f ? 1u : 0u) << ci;
    outw[co * 72 + wd * 9 + tap] = s;
}

__global__ void k_prep_bn(const float* __restrict__ g, const float* __restrict__ b,
                          const float* __restrict__ m, const float* __restrict__ v,
                          int which) {
    int c = threadIdx.x;
    float sc = g[c] * rsqrtf(v[c] + BN_EPS);
    float sh = b[c] - m[c] * sc;
    if (which) { g_sc2[c] = sc; g_sh2[c] = sh; }
    else       { g_sc1[c] = sc; g_sh1[c] = sh; }
}

// Co-stationary binary conv: lane = output channel, weights register-resident.
// Direct POPC per mask word (no CSA), accumulated via mad.lo on the fma pipe
// across 3 independent chains per pixel. w unrolled x2 (shared window cols).
template <int STAGE>
__global__ __launch_bounds__(256, 2) void k_bconv(
    const float* __restrict__ xres, float* __restrict__ out) {
    const uint2* __restrict__ pin = (STAGE == 1) ? g_p1 : g_p2;
    const uint32_t* __restrict__ wb = (STAGE == 1) ? g_wb1 : g_wb2;

    extern __shared__ char sm[];
    uint2* tile = (uint2*)sm;                 // [wd][TR][58]
    int* zc = (int*)(sm + ZC_OFF);            // [TR*58]
    int* sbase = (int*)(sm + SB_OFF);         // [TB*56]
    float* stg = (float*)(sm + STG_OFF);      // conv2: [C][57]

    const int rg = blockIdx.x, n = blockIdx.y, tid = threadIdx.x;
    const int h0 = rg * TB;
    const int lane = tid & 31, wid = tid >> 5;
    const int co = wid * 32 + lane;

    // Per-lane weights (72 words) and BN coefficients: register-resident.
    uint32_t wk[72];
#pragma unroll
    for (int t = 0; t < 72; t++) wk[t] = __ldg(wb + co * 72 + t);
    const float sc = __ldg(((STAGE == 1) ? g_sc1 : g_sc2) + co);
    const float sh = __ldg(((STAGE == 1) ? g_sh1 : g_sh2) + co);

    // Load tile as uint4 (pairs of uint2); layout is [pix][wd], wd even-aligned.
    for (int i = tid; i < WORDS * TRPD / 2; i += 256) {
        int wd2 = i & 3, p = i >> 2;   // wd2 = wd/2
        uint4 v = ((const uint4*)(pin + (((size_t)n * PD + h0) * PD) * WORDS))[p * 4 + wd2];
        uint2* dst0 = tile + (2 * wd2) * TRPD + p;
        dst0[0] = make_uint2(v.x, v.y);
        dst0[TRPD] = make_uint2(v.z, v.w);
    }
    __syncthreads();
    // zc[p] = sum_wd popc(z)
    for (int p = tid; p < TRPD; p += 256) {
        int s = 0;
#pragma unroll
        for (int wd = 0; wd < 8; wd++) s += __popc(tile[wd * TRPD + p].y);
        zc[p] = s;
    }
    __syncthreads();
    // sbase[pixel] = 3x3 box-sum of zc (warp-uniform "base" term)
    for (int p = tid; p < TB * W; p += 256) {
        int r = p / W, w = p - r * W;
        int s = 0;
#pragma unroll
        for (int dh = 0; dh < 3; dh++)
#pragma unroll
            for (int dw = 0; dw < 3; dw++) s += zc[(r + dh) * PD + w + dw];
        sbase[p] = s;
    }
    __syncthreads();

    for (int r = 0; r < TB; r++) {
#pragma unroll 1
        for (int w = 0; w < W; w += 2) {
            int a00 = 0, a01 = 0, a02 = 0;   // pixel w: 3 chains
            int a10 = 0, a11 = 0, a12 = 0;   // pixel w+1: 3 chains
#pragma unroll
            for (int wd = 0; wd < 8; wd++) {
                const uint2* tp = tile + wd * TRPD + r * PD + w;
                uint2 xa0 = tp[0], xa1 = tp[1], xa2 = tp[2], xa3 = tp[3];
                uint2 xb0 = tp[PD], xb1 = tp[PD + 1], xb2 = tp[PD + 2], xb3 = tp[PD + 3];
                uint2 xc0 = tp[2 * PD], xc1 = tp[2 * PD + 1], xc2 = tp[2 * PD + 2],
                      xc3 = tp[2 * PD + 3];
                const uint32_t* wq = wk + wd * 9;
                // pixel w: direct popc, 3 chains (one per kernel row)
                madacc1(a00, __popc(xa0.y & (xa0.x ^ wq[0])));
                madacc1(a01, __popc(xb0.y & (xb0.x ^ wq[3])));
                madacc1(a02, __popc(xc0.y & (xc0.x ^ wq[6])));
                madacc1(a00, __popc(xa1.y & (xa1.x ^ wq[1])));
                madacc1(a01, __popc(xb1.y & (xb1.x ^ wq[4])));
                madacc1(a02, __popc(xc1.y & (xc1.x ^ wq[7])));
                madacc1(a00, __popc(xa2.y & (xa2.x ^ wq[2])));
                madacc1(a01, __popc(xb2.y & (xb2.x ^ wq[5])));
                madacc1(a02, __popc(xc2.y & (xc2.x ^ wq[8])));
                // pixel w+1
                madacc1(a10, __popc(xa1.y & (xa1.x ^ wq[0])));
                madacc1(a11, __popc(xb1.y & (xb1.x ^ wq[3])));
                madacc1(a12, __popc(xc1.y & (xc1.x ^ wq[6])));
                madacc1(a10, __popc(xa2.y & (xa2.x ^ wq[1])));
                madacc1(a11, __popc(xb2.y & (xb2.x ^ wq[4])));
                madacc1(a12, __popc(xc2.y & (xc2.x ^ wq[7])));
                madacc1(a10, __popc(xa3.y & (xa3.x ^ wq[2])));
                madacc1(a11, __popc(xb3.y & (xb3.x ^ wq[5])));
                madacc1(a12, __popc(xc3.y & (xc3.x ^ wq[8])));
            }
            int acc0 = a00 + a01;  madacc1(acc0, a02);
            int acc1 = a10 + a11;  madacc1(acc1, a12);
            const int dot0 = madn2(acc0, sbase[r * W + w]);
            const int dot1 = madn2(acc1, sbase[r * W + w + 1]);
            const float t0 = fmaf((float)dot0, sc, sh);
            const float t1 = fmaf((float)dot1, sc, sh);
            if (STAGE == 1) {
                uint32_t sig0 = __ballot_sync(0xffffffffu, t0 > 0.f);
                uint32_t nz0 = __ballot_sync(0xffffffffu, t0 != 0.f);
                uint32_t sig1 = __ballot_sync(0xffffffffu, t1 > 0.f);
                uint32_t nz1 = __ballot_sync(0xffffffffu, t1 != 0.f);
                if (lane == 0) {
                    size_t gi = (((size_t)n * PD + (h0 + r + 1)) * PD + (w + 1)) * WORDS + wid;
                    g_p2[gi] = make_uint2(sig0, nz0);
                    g_p2[gi + WORDS] = make_uint2(sig1, nz1);
                }
            } else {
                stg[co * 57 + w] = t0;
                stg[co * 57 + w + 1] = t1;
            }
        }
        if (STAGE == 2) {
            __syncthreads();
            const int h = h0 + r;
            for (int i = tid; i < C * W; i += 256) {
                int c2 = i / W, w2 = i - c2 * W;
                size_t oi = (((size_t)n * C + c2) * H + h) * W + w2;
                float v = stg[c2 * 57 + w2] + xres[oi];
                out[oi] = fminf(1.f, fmaxf(-1.f, v));
            }
            __syncthreads();
        }
    }
}

extern "C" void kernel_launch(void* const* d_in, const int* in_sizes, int n_in,
                              void* d_out, int out_size) {
    (void)in_sizes; (void)n_in; (void)out_size;
    const float* x = (const float*)d_in[0];
    const float* w1 = (const float*)d_in[1];
    const float* g1 = (const float*)d_in[2];
    const float* b1 = (const float*)d_in[3];
    const float* m1 = (const float*)d_in[4];
    const float* v1 = (const float*)d_in[5];
    const float* w2 = (const float*)d_in[6];
    const float* g2 = (const float*)d_in[7];
    const float* b2 = (const float*)d_in[8];
    const float* m2 = (const float*)d_in[9];
    const float* v2 = (const float*)d_in[10];
    float* out = (float*)d_out;

    cudaFuncSetAttribute(k_bconv<1>, cudaFuncAttributeMaxDynamicSharedMemorySize, DYN1);
    cudaFuncSetAttribute(k_bconv<2>, cudaFuncAttributeMaxDynamicSharedMemorySize, DYN2);

    dim3 grid(H / TB, Nn);
    k_zero<<<2048, 256>>>();
    k_pack_x<<<dim3(H, Nn), dim3(W, WORDS)>>>(x);
    k_pack_w<<<C, dim3(WORDS, 9)>>>(w1, 0);
    k_pack_w<<<C, dim3(WORDS, 9)>>>(w2, 1);
    k_prep_bn<<<1, C>>>(g1, b1, m1, v1, 0);
    k_bconv<1><<<grid, 256, DYN1>>>(x, out);
    k_prep_bn<<<1, C>>>(g2, b2, m2, v2, 1);
    k_bconv<2><<<grid, 256, DYN2>>>(x, out);
}

// round 15
// speedup vs baseline: 1.1999x; 1.1999x over previous
#include <cuda_runtime.h>
#include <stdint.h>

#define BN_EPS 1e-5f

namespace {
constexpr int Nn = 64, C = 256, H = 56, W = 56;
constexpr int PD = 58;             // padded dim
constexpr int WORDS = 8;           // channel words
constexpr int TB = 4;              // output rows per block
constexpr int TR = TB + 2;         // tile rows (with halo)
constexpr int TRPD = TR * PD;      // 348
constexpr int TILE_U2 = WORDS * TRPD;             // 2784 uint2
constexpr int ZC_OFF = TILE_U2 * 8;               // 22272 B
constexpr int SB_OFF = ZC_OFF + TRPD * 4;         // 23664
constexpr int STG_OFF = SB_OFF + TB * W * 4;      // 24560
constexpr int DYN1 = STG_OFF;                     // conv1
constexpr int DYN2 = STG_OFF + C * 57 * 4;        // conv2: 82928 B
constexpr int NBORD = 4 * PD - 4;                 // 228 border pixels
}

// Packed (sign, nonzero) bitplanes, zero-padded borders. uint2 = (s, z).
__device__ uint2 g_p1[(size_t)Nn * PD * PD * WORDS];
__device__ uint2 g_p2[(size_t)Nn * PD * PD * WORDS];
__device__ uint32_t g_wb1[C * 72];   // [co][wd][tap]
__device__ uint32_t g_wb2[C * 72];
__device__ float g_sc1[C], g_sh1[C], g_sc2[C], g_sh2[C];

__device__ __forceinline__ void fa(uint32_t a, uint32_t b, uint32_t c,
                                   uint32_t& s, uint32_t& cy) {
    s = a ^ b ^ c;
    cy = (a & b) | (c & (a | b));
}
__device__ __forceinline__ void ha(uint32_t a, uint32_t b, uint32_t& s, uint32_t& cy) {
    s = a ^ b;
    cy = a & b;
}
__device__ __forceinline__ void madacc1(int& a, int p) {
    asm("mad.lo.s32 %0, %1, 1, %0;" : "+r"(a) : "r"(p));
}
__device__ __forceinline__ void madacc2(int& a, int p) {
    asm("mad.lo.s32 %0, %1, 2, %0;" : "+r"(a) : "r"(p));
}
__device__ __forceinline__ void madacc4(int& a, int p) {
    asm("mad.lo.s32 %0, %1, 4, %0;" : "+r"(a) : "r"(p));
}
__device__ __forceinline__ void madacc8(int& a, int p) {
    asm("mad.lo.s32 %0, %1, 8, %0;" : "+r"(a) : "r"(p));
}
__device__ __forceinline__ void madacc16(int& a, int p) {
    asm("mad.lo.s32 %0, %1, 16, %0;" : "+r"(a) : "r"(p));
}
__device__ __forceinline__ void madacc32(int& a, int p) {
    asm("mad.lo.s32 %0, %1, 32, %0;" : "+r"(a) : "r"(p));
}
__device__ __forceinline__ int madn2(int acc, int d0) {
    int r;
    asm("mad.lo.s32 %0, %1, -2, %2;" : "=r"(r) : "r"(acc), "r"(d0));
    return r;
}

// One wd's 9 masks -> {S(w1), C2(w2), S2(w2), C4(w4)}: 5 FA, no popc.
__device__ __forceinline__ void wd_comp(uint32_t m0, uint32_t m1, uint32_t m2,
                                        uint32_t m3, uint32_t m4, uint32_t m5,
                                        uint32_t m6, uint32_t m7, uint32_t m8,
                                        uint32_t o[4]) {
    uint32_t s0, c0, s1, c1, s2, c2;
    fa(m0, m1, m2, s0, c0);
    fa(m3, m4, m5, s1, c1);
    fa(m6, m7, m8, s2, c2);
    fa(s0, s1, s2, o[0], o[1]);   // S (w1), C2 (w2)
    fa(c0, c1, c2, o[2], o[3]);   // S2 (w2), C4 (w4)
}

// Merge two wd outputs -> {o1(w1), o2(w2), o4(w4), o8a(w8), o8b(w8)}: 10 LOP3.
__device__ __forceinline__ void pairm(const uint32_t a[4], const uint32_t b[4],
                                      uint32_t o[5]) {
    uint32_t g1, h2, g2, g3, h4;
    ha(a[0], b[0], o[0], g1);        // w1, carry w2
    fa(a[1], a[2], b[1], h2, g2);    // w2, carry w4
    fa(b[2], g1, h2, o[1], g3);      // w2 final, carry w4
    fa(a[3], b[3], g2, h4, o[3]);    // w4, carry w8
    ha(g3, h4, o[2], o[4]);          // w4 final, carry w8
}

// Merge two pair outputs and popc-accumulate: 12 LOP3 + 6 POPC.
__device__ __forceinline__ void quadm(const uint32_t A[5], const uint32_t B[5],
                                      int& tot) {
    uint32_t u1, k1, u2, k2, u4, k4, v8, k8a, u8, k8b, u16, k32;
    ha(A[0], B[0], u1, k1);
    fa(A[1], B[1], k1, u2, k2);
    fa(A[2], B[2], k2, u4, k4);
    fa(A[3], A[4], B[3], v8, k8a);
    fa(B[4], k4, v8, u8, k8b);
    ha(k8a, k8b, u16, k32);
    madacc1(tot, __popc(u1));
    madacc2(tot, __popc(u2));
    madacc4(tot, __popc(u4));
    madacc8(tot, __popc(u8));
    madacc16(tot, __popc(u16));
    madacc32(tot, __popc(k32));
}

// Zero only border pixels (interiors fully rewritten by pack_x / conv1).
__global__ void k_zero_border() {
    const int n = blockIdx.x, tid = threadIdx.x;
    for (int i = tid; i < NBORD * WORDS; i += 256) {
        int b = i >> 3, wd = i & 7;
        int ph, pw;
        if (b < PD) { ph = 0; pw = b; }
        else if (b < 2 * PD) { ph = PD - 1; pw = b - PD; }
        else if (b < 2 * PD + (PD - 2)) { ph = b - 2 * PD + 1; pw = 0; }
        else { ph = b - (2 * PD + PD - 2) + 1; pw = PD - 1; }
        size_t gi = (((size_t)n * PD + ph) * PD + pw) * WORDS + wd;
        g_p1[gi] = make_uint2(0u, 0u);
        g_p2[gi] = make_uint2(0u, 0u);
    }
}

// grid (H, N), block (W=56, WORDS=8)
__global__ void k_pack_x(const float* __restrict__ x) {
    const int h = blockIdx.x, n = blockIdx.y;
    const int w = threadIdx.x, wd = threadIdx.y;
    const float* xp = x + (((size_t)n * C + wd * 32) * H + h) * W + w;
    uint32_t s = 0, z = 0;
#pragma unroll
    for (int ci = 0; ci < 32; ci++) {
        float v = xp[(size_t)ci * (H * W)];
        s |= (v > 0.f ? 1u : 0u) << ci;
        z |= (v != 0.f ? 1u : 0u) << ci;
    }
    g_p1[(((size_t)n * PD + (h + 1)) * PD + (w + 1)) * WORDS + wd] = make_uint2(s, z);
}

// grid C, block (WORDS=8, 9): layout [co][wd][tap]
__global__ void k_pack_w(const float* __restrict__ w, int which) {
    uint32_t* __restrict__ outw = which ? g_wb2 : g_wb1;
    const int co = blockIdx.x, wd = threadIdx.x, tap = threadIdx.y;
    uint32_t s = 0;
#pragma unroll
    for (int ci = 0; ci < 32; ci++)
        s |= (w[(((size_t)co * C) + wd * 32 + ci) * 9 + tap] > 0.f ? 1u : 0u) << ci;
    outw[co * 72 + wd * 9 + tap] = s;
}

__global__ void k_prep_bn(const float* __restrict__ g, const float* __restrict__ b,
                          const float* __restrict__ m, const float* __restrict__ v,
                          int which) {
    int c = threadIdx.x;
    float sc = g[c] * rsqrtf(v[c] + BN_EPS);
    float sh = b[c] - m[c] * sc;
    if (which) { g_sc2[c] = sc; g_sh2[c] = sh; }
    else       { g_sc1[c] = sc; g_sh1[c] = sh; }
}

// Co-stationary binary conv. STAGE 1: deep CSA tree (12 popc/pixel).
// STAGE 2: proven R12 path (per-wd CSA, 32 popc/pixel).
template <int STAGE>
__global__ void
#if 1
__launch_bounds__(256, (STAGE == 2) ? 2 : 0)
#endif
k_bconv(const float* __restrict__ xres, float* __restrict__ out) {
    const uint2* __restrict__ pin = (STAGE == 1) ? g_p1 : g_p2;
    const uint32_t* __restrict__ wb = (STAGE == 1) ? g_wb1 : g_wb2;

    extern __shared__ char sm[];
    uint2* tile = (uint2*)sm;                 // [wd][TR][58]
    int* zc = (int*)(sm + ZC_OFF);            // [TR*58]
    int* sbase = (int*)(sm + SB_OFF);         // [TB*56]
    float* stg = (float*)(sm + STG_OFF);      // conv2: [C][57]

    const int rg = blockIdx.x, n = blockIdx.y, tid = threadIdx.x;
    const int h0 = rg * TB;
    const int lane = tid & 31, wid = tid >> 5;
    const int co = wid * 32 + lane;

    uint32_t wk[72];
#pragma unroll
    for (int t = 0; t < 72; t++) wk[t] = __ldg(wb + co * 72 + t);
    const float sc = __ldg(((STAGE == 1) ? g_sc1 : g_sc2) + co);
    const float sh = __ldg(((STAGE == 1) ? g_sh1 : g_sh2) + co);

    for (int i = tid; i < WORDS * TRPD / 2; i += 256) {
        int wd2 = i & 3, p = i >> 2;
        uint4 v = ((const uint4*)(pin + (((size_t)n * PD + h0) * PD) * WORDS))[p * 4 + wd2];
        uint2* dst0 = tile + (2 * wd2) * TRPD + p;
        dst0[0] = make_uint2(v.x, v.y);
        dst0[TRPD] = make_uint2(v.z, v.w);
    }
    __syncthreads();
    for (int p = tid; p < TRPD; p += 256) {
        int s = 0;
#pragma unroll
        for (int wd = 0; wd < 8; wd++) s += __popc(tile[wd * TRPD + p].y);
        zc[p] = s;
    }
    __syncthreads();
    for (int p = tid; p < TB * W; p += 256) {
        int r = p / W, w = p - r * W;
        int s = 0;
#pragma unroll
        for (int dh = 0; dh < 3; dh++)
#pragma unroll
            for (int dw = 0; dw < 3; dw++) s += zc[(r + dh) * PD + w + dw];
        sbase[p] = s;
    }
    __syncthreads();

    for (int r = 0; r < TB; r++) {
#pragma unroll 1
        for (int w = 0; w < W; w += 2) {
            int tot0 = 0, tot1 = 0;
            if (STAGE == 1) {
                // --- deep tree: per-wd CSA -> pair merge -> quad merge ---
                uint32_t pp0[5], pp1[5];
#pragma unroll
                for (int wp = 0; wp < 4; wp++) {
                    uint32_t A0[4], B0[4], A1[4], B1[4];
#pragma unroll
                    for (int hh = 0; hh < 2; hh++) {
                        const int wd = 2 * wp + hh;
                        const uint2* tp = tile + wd * TRPD + r * PD + w;
                        uint2 xa0 = tp[0], xa1 = tp[1], xa2 = tp[2], xa3 = tp[3];
                        uint2 xb0 = tp[PD], xb1 = tp[PD + 1], xb2 = tp[PD + 2],
                              xb3 = tp[PD + 3];
                        uint2 xc0 = tp[2 * PD], xc1 = tp[2 * PD + 1],
                              xc2 = tp[2 * PD + 2], xc3 = tp[2 * PD + 3];
                        const uint32_t* wq = wk + wd * 9;
                        wd_comp(xa0.y & (xa0.x ^ wq[0]), xa1.y & (xa1.x ^ wq[1]),
                                xa2.y & (xa2.x ^ wq[2]), xb0.y & (xb0.x ^ wq[3]),
                                xb1.y & (xb1.x ^ wq[4]), xb2.y & (xb2.x ^ wq[5]),
                                xc0.y & (xc0.x ^ wq[6]), xc1.y & (xc1.x ^ wq[7]),
                                xc2.y & (xc2.x ^ wq[8]), hh ? B0 : A0);
                        wd_comp(xa1.y & (xa1.x ^ wq[0]), xa2.y & (xa2.x ^ wq[1]),
                                xa3.y & (xa3.x ^ wq[2]), xb1.y & (xb1.x ^ wq[3]),
                                xb2.y & (xb2.x ^ wq[4]), xb3.y & (xb3.x ^ wq[5]),
                                xc1.y & (xc1.x ^ wq[6]), xc2.y & (xc2.x ^ wq[7]),
                                xc3.y & (xc3.x ^ wq[8]), hh ? B1 : A1);
                    }
                    uint32_t cur0[5], cur1[5];
                    pairm(A0, B0, cur0);
                    pairm(A1, B1, cur1);
                    if ((wp & 1) == 0) {
#pragma unroll
                        for (int q = 0; q < 5; q++) { pp0[q] = cur0[q]; pp1[q] = cur1[q]; }
                    } else {
                        quadm(pp0, cur0, tot0);
                        quadm(pp1, cur1, tot1);
                    }
                }
            } else {
                // --- proven R12 path: per-wd CSA + 4 popc ---
#pragma unroll
                for (int wd = 0; wd < 8; wd++) {
                    const uint2* tp = tile + wd * TRPD + r * PD + w;
                    uint2 xa0 = tp[0], xa1 = tp[1], xa2 = tp[2], xa3 = tp[3];
                    uint2 xb0 = tp[PD], xb1 = tp[PD + 1], xb2 = tp[PD + 2], xb3 = tp[PD + 3];
                    uint2 xc0 = tp[2 * PD], xc1 = tp[2 * PD + 1], xc2 = tp[2 * PD + 2],
                          xc3 = tp[2 * PD + 3];
                    const uint32_t* wq = wk + wd * 9;
                    {
                        uint32_t o[4];
                        wd_comp(xa0.y & (xa0.x ^ wq[0]), xa1.y & (xa1.x ^ wq[1]),
                                xa2.y & (xa2.x ^ wq[2]), xb0.y & (xb0.x ^ wq[3]),
                                xb1.y & (xb1.x ^ wq[4]), xb2.y & (xb2.x ^ wq[5]),
                                xc0.y & (xc0.x ^ wq[6]), xc1.y & (xc1.x ^ wq[7]),
                                xc2.y & (xc2.x ^ wq[8]), o);
                        madacc1(tot0, __popc(o[0]));
                        madacc2(tot0, __popc(o[1]));
                        madacc2(tot0, __popc(o[2]));
                        madacc4(tot0, __popc(o[3]));
                    }
                    {
                        uint32_t o[4];
                        wd_comp(xa1.y & (xa1.x ^ wq[0]), xa2.y & (xa2.x ^ wq[1]),
                                xa3.y & (xa3.x ^ wq[2]), xb1.y & (xb1.x ^ wq[3]),
                                xb2.y & (xb2.x ^ wq[4]), xb3.y & (xb3.x ^ wq[5]),
                                xc1.y & (xc1.x ^ wq[6]), xc2.y & (xc2.x ^ wq[7]),
                                xc3.y & (xc3.x ^ wq[8]), o);
                        madacc1(tot1, __popc(o[0]));
                        madacc2(tot1, __popc(o[1]));
                        madacc2(tot1, __popc(o[2]));
                        madacc4(tot1, __popc(o[3]));
                    }
                }
            }

            const int dot0 = madn2(tot0, sbase[r * W + w]);
            const int dot1 = madn2(tot1, sbase[r * W + w + 1]);
            const float t0 = fmaf((float)dot0, sc, sh);
            const float t1 = fmaf((float)dot1, sc, sh);
            if (STAGE == 1) {
                uint32_t sig0 = __ballot_sync(0xffffffffu, t0 > 0.f);
                uint32_t nz0 = __ballot_sync(0xffffffffu, t0 != 0.f);
                uint32_t sig1 = __ballot_sync(0xffffffffu, t1 > 0.f);
                uint32_t nz1 = __ballot_sync(0xffffffffu, t1 != 0.f);
                if (lane == 0) {
                    size_t gi = (((size_t)n * PD + (h0 + r + 1)) * PD + (w + 1)) * WORDS + wid;
                    g_p2[gi] = make_uint2(sig0, nz0);
                    g_p2[gi + WORDS] = make_uint2(sig1, nz1);
                }
            } else {
                stg[co * 57 + w] = t0;
                stg[co * 57 + w + 1] = t1;
            }
        }
        if (STAGE == 2) {
            __syncthreads();
            const int h = h0 + r;
            for (int i = tid; i < C * W; i += 256) {
                int c2 = i / W, w2 = i - c2 * W;
                size_t oi = (((size_t)n * C + c2) * H + h) * W + w2;
                float v = stg[c2 * 57 + w2] + xres[oi];
                out[oi] = fminf(1.f, fmaxf(-1.f, v));
            }
            __syncthreads();
        }
    }
}

extern "C" void kernel_launch(void* const* d_in, const int* in_sizes, int n_in,
                              void* d_out, int out_size) {
    (void)in_sizes; (void)n_in; (void)out_size;
    const float* x = (const float*)d_in[0];
    const float* w1 = (const float*)d_in[1];
    const float* g1 = (const float*)d_in[2];
    const float* b1 = (const float*)d_in[3];
    const float* m1 = (const float*)d_in[4];
    const float* v1 = (const float*)d_in[5];
    const float* w2 = (const float*)d_in[6];
    const float* g2 = (const float*)d_in[7];
    const float* b2 = (const float*)d_in[8];
    const float* m2 = (const float*)d_in[9];
    const float* v2 = (const float*)d_in[10];
    float* out = (float*)d_out;

    cudaFuncSetAttribute(k_bconv<1>, cudaFuncAttributeMaxDynamicSharedMemorySize, DYN1);
    cudaFuncSetAttribute(k_bconv<2>, cudaFuncAttributeMaxDynamicSharedMemorySize, DYN2);

    dim3 grid(H / TB, Nn);
    k_zero_border<<<Nn, 256>>>();
    k_pack_x<<<dim3(H, Nn), dim3(W, WORDS)>>>(x);
    k_pack_w<<<C, dim3(WORDS, 9)>>>(w1, 0);
    k_pack_w<<<C, dim3(WORDS, 9)>>>(w2, 1);
    k_prep_bn<<<1, C>>>(g1, b1, m1, v1, 0);
    k_bconv<1><<<grid, 256, DYN1>>>(x, out);
    k_prep_bn<<<1, C>>>(g2, b2, m2, v2, 1);
    k_bconv<2><<<grid, 256, DYN2>>>(x, out);
}

// round 16
// speedup vs baseline: 1.3822x; 1.1520x over previous
#include <cuda_runtime.h>
#include <stdint.h>

#define BN_EPS 1e-5f

namespace {
constexpr int Nn = 64, C = 256, H = 56, W = 56;
constexpr int PD = 58;             // padded dim
constexpr int WORDS = 8;           // channel words
constexpr int TB = 4;              // output rows per block
constexpr int TR = TB + 2;         // tile rows (with halo)
constexpr int TRPD = TR * PD;      // 348
constexpr int TILE_U2 = WORDS * TRPD;             // 2784 uint2
constexpr int ZC_OFF = TILE_U2 * 8;               // 22272 B
constexpr int SB_OFF = ZC_OFF + TRPD * 4;         // 23664
constexpr int STG_OFF = SB_OFF + TB * W * 4;      // 24560
constexpr int DYN1 = STG_OFF;                     // conv1: 24560 B
constexpr int DYN2 = STG_OFF + C * 57 * 4;        // conv2: 82928 B
constexpr int NBORD = 4 * PD - 4;                 // 228 border pixels
}

// Packed (sign, nonzero) bitplanes, zero-padded borders. uint2 = (s, z).
__device__ uint2 g_p1[(size_t)Nn * PD * PD * WORDS];
__device__ uint2 g_p2[(size_t)Nn * PD * PD * WORDS];
__device__ uint32_t g_wb1[C * 72];   // [co][wd][tap]
__device__ uint32_t g_wb2[C * 72];
__device__ float g_sc1[C], g_sh1[C], g_sc2[C], g_sh2[C];

__device__ __forceinline__ void fa(uint32_t a, uint32_t b, uint32_t c,
                                   uint32_t& s, uint32_t& cy) {
    s = a ^ b ^ c;
    cy = (a & b) | (c & (a | b));
}
__device__ __forceinline__ void madacc1(int& a, int p) {  // a += p (fma pipe)
    asm("mad.lo.s32 %0, %1, 1, %0;" : "+r"(a) : "r"(p));
}
__device__ __forceinline__ void madacc2(int& a, int p) {  // a += 2*p (fma pipe)
    asm("mad.lo.s32 %0, %1, 2, %0;" : "+r"(a) : "r"(p));
}
__device__ __forceinline__ void madacc4(int& a, int p) {  // a += 4*p (fma pipe)
    asm("mad.lo.s32 %0, %1, 4, %0;" : "+r"(a) : "r"(p));
}
__device__ __forceinline__ int madn2(int acc, int d0) {   // d0 - 2*acc (fma pipe)
    int r;
    asm("mad.lo.s32 %0, %1, -2, %2;" : "=r"(r) : "r"(acc), "r"(d0));
    return r;
}

// Zero only border pixels (interiors fully rewritten by pack_x / conv1).
__global__ void k_zero_border() {
    const int n = blockIdx.x, tid = threadIdx.x;
    for (int i = tid; i < NBORD * WORDS; i += 256) {
        int b = i >> 3, wd = i & 7;
        int ph, pw;
        if (b < PD) { ph = 0; pw = b; }
        else if (b < 2 * PD) { ph = PD - 1; pw = b - PD; }
        else if (b < 2 * PD + (PD - 2)) { ph = b - 2 * PD + 1; pw = 0; }
        else { ph = b - (2 * PD + PD - 2) + 1; pw = PD - 1; }
        size_t gi = (((size_t)n * PD + ph) * PD + pw) * WORDS + wd;
        g_p1[gi] = make_uint2(0u, 0u);
        g_p2[gi] = make_uint2(0u, 0u);
    }
}

// grid (H, N), block (W=56, WORDS=8)
__global__ void k_pack_x(const float* __restrict__ x) {
    const int h = blockIdx.x, n = blockIdx.y;
    const int w = threadIdx.x, wd = threadIdx.y;
    const float* xp = x + (((size_t)n * C + wd * 32) * H + h) * W + w;
    uint32_t s = 0, z = 0;
#pragma unroll
    for (int ci = 0; ci < 32; ci++) {
        float v = xp[(size_t)ci * (H * W)];
        s |= (v > 0.f ? 1u : 0u) << ci;
        z |= (v != 0.f ? 1u : 0u) << ci;
    }
    g_p1[(((size_t)n * PD + (h + 1)) * PD + (w + 1)) * WORDS + wd] = make_uint2(s, z);
}

// grid C, block (WORDS=8, 9): layout [co][wd][tap]
__global__ void k_pack_w(const float* __restrict__ w, int which) {
    uint32_t* __restrict__ outw = which ? g_wb2 : g_wb1;
    const int co = blockIdx.x, wd = threadIdx.x, tap = threadIdx.y;
    uint32_t s = 0;
#pragma unroll
    for (int ci = 0; ci < 32; ci++)
        s |= (w[(((size_t)co * C) + wd * 32 + ci) * 9 + tap] > 0.f ? 1u : 0u) << ci;
    outw[co * 72 + wd * 9 + tap] = s;
}

__global__ void k_prep_bn(const float* __restrict__ g, const float* __restrict__ b,
                          const float* __restrict__ m, const float* __restrict__ v,
                          int which) {
    int c = threadIdx.x;
    float sc = g[c] * rsqrtf(v[c] + BN_EPS);
    float sh = b[c] - m[c] * sc;
    if (which) { g_sc2[c] = sc; g_sh2[c] = sh; }
    else       { g_sc1[c] = sc; g_sh1[c] = sh; }
}

// Co-stationary binary conv (R12 arithmetic): lane = output channel, weights
// register-resident, per-wd 5-FA CSA + 4 POPC, w unrolled x2.
// Window loads vectorized as LDS.128 (uint4 = two adjacent uint2 columns).
template <int STAGE>
__global__ __launch_bounds__(256, 2) void k_bconv(
    const float* __restrict__ xres, float* __restrict__ out) {
    const uint2* __restrict__ pin = (STAGE == 1) ? g_p1 : g_p2;
    const uint32_t* __restrict__ wb = (STAGE == 1) ? g_wb1 : g_wb2;

    extern __shared__ char sm[];
    uint2* tile = (uint2*)sm;                 // [wd][TR][58]
    int* zc = (int*)(sm + ZC_OFF);            // [TR*58]
    int* sbase = (int*)(sm + SB_OFF);         // [TB*56]
    float* stg = (float*)(sm + STG_OFF);      // conv2: [C][57]

    const int rg = blockIdx.x, n = blockIdx.y, tid = threadIdx.x;
    const int h0 = rg * TB;
    const int lane = tid & 31, wid = tid >> 5;
    const int co = wid * 32 + lane;

    // Per-lane weights (72 words) and BN coefficients: register-resident.
    uint32_t wk[72];
#pragma unroll
    for (int t = 0; t < 72; t++) wk[t] = __ldg(wb + co * 72 + t);
    const float sc = __ldg(((STAGE == 1) ? g_sc1 : g_sc2) + co);
    const float sh = __ldg(((STAGE == 1) ? g_sh1 : g_sh2) + co);

    // Load tile as uint4 (pairs of uint2); layout is [pix][wd], wd even-aligned.
    for (int i = tid; i < WORDS * TRPD / 2; i += 256) {
        int wd2 = i & 3, p = i >> 2;   // wd2 = wd/2
        uint4 v = ((const uint4*)(pin + (((size_t)n * PD + h0) * PD) * WORDS))[p * 4 + wd2];
        uint2* dst0 = tile + (2 * wd2) * TRPD + p;
        dst0[0] = make_uint2(v.x, v.y);
        dst0[TRPD] = make_uint2(v.z, v.w);
    }
    __syncthreads();
    // zc[p] = sum_wd popc(z)
    for (int p = tid; p < TRPD; p += 256) {
        int s = 0;
#pragma unroll
        for (int wd = 0; wd < 8; wd++) s += __popc(tile[wd * TRPD + p].y);
        zc[p] = s;
    }
    __syncthreads();
    // sbase[pixel] = 3x3 box-sum of zc (warp-uniform "base" term)
    for (int p = tid; p < TB * W; p += 256) {
        int r = p / W, w = p - r * W;
        int s = 0;
#pragma unroll
        for (int dh = 0; dh < 3; dh++)
#pragma unroll
            for (int dw = 0; dw < 3; dw++) s += zc[(r + dh) * PD + w + dw];
        sbase[p] = s;
    }
    __syncthreads();

    for (int r = 0; r < TB; r++) {
#pragma unroll 1
        for (int w = 0; w < W; w += 2) {
            int acc0 = 0, acc1 = 0;
#pragma unroll
            for (int wd = 0; wd < 8; wd++) {
                const uint2* tp = tile + wd * TRPD + r * PD + w;
                // LDS.128: two adjacent (s,z) columns per load; w even -> aligned.
                uint4 va0 = *(const uint4*)(tp);
                uint4 va1 = *(const uint4*)(tp + 2);
                uint4 vb0 = *(const uint4*)(tp + PD);
                uint4 vb1 = *(const uint4*)(tp + PD + 2);
                uint4 vc0 = *(const uint4*)(tp + 2 * PD);
                uint4 vc1 = *(const uint4*)(tp + 2 * PD + 2);
                uint2 xa0 = make_uint2(va0.x, va0.y), xa1 = make_uint2(va0.z, va0.w);
                uint2 xa2 = make_uint2(va1.x, va1.y), xa3 = make_uint2(va1.z, va1.w);
                uint2 xb0 = make_uint2(vb0.x, vb0.y), xb1 = make_uint2(vb0.z, vb0.w);
                uint2 xb2 = make_uint2(vb1.x, vb1.y), xb3 = make_uint2(vb1.z, vb1.w);
                uint2 xc0 = make_uint2(vc0.x, vc0.y), xc1 = make_uint2(vc0.z, vc0.w);
                uint2 xc2 = make_uint2(vc1.x, vc1.y), xc3 = make_uint2(vc1.z, vc1.w);
                const uint32_t* wq = wk + wd * 9;
                // pixel w
                {
                    uint32_t m0 = xa0.y & (xa0.x ^ wq[0]);
                    uint32_t m1 = xa1.y & (xa1.x ^ wq[1]);
                    uint32_t m2 = xa2.y & (xa2.x ^ wq[2]);
                    uint32_t m3 = xb0.y & (xb0.x ^ wq[3]);
                    uint32_t m4 = xb1.y & (xb1.x ^ wq[4]);
                    uint32_t m5 = xb2.y & (xb2.x ^ wq[5]);
                    uint32_t m6 = xc0.y & (xc0.x ^ wq[6]);
                    uint32_t m7 = xc1.y & (xc1.x ^ wq[7]);
                    uint32_t m8 = xc2.y & (xc2.x ^ wq[8]);
                    uint32_t s0, c0, s1, c1, s2, c2, S, C2, S2, C4;
                    fa(m0, m1, m2, s0, c0);
                    fa(m3, m4, m5, s1, c1);
                    fa(m6, m7, m8, s2, c2);
                    fa(s0, s1, s2, S, C2);
                    fa(c0, c1, c2, S2, C4);
                    madacc1(acc0, __popc(S));
                    madacc2(acc0, __popc(C2));
                    madacc2(acc0, __popc(S2));
                    madacc4(acc0, __popc(C4));
                }
                // pixel w+1
                {
                    uint32_t m0 = xa1.y & (xa1.x ^ wq[0]);
                    uint32_t m1 = xa2.y & (xa2.x ^ wq[1]);
                    uint32_t m2 = xa3.y & (xa3.x ^ wq[2]);
                    uint32_t m3 = xb1.y & (xb1.x ^ wq[3]);
                    uint32_t m4 = xb2.y & (xb2.x ^ wq[4]);
                    uint32_t m5 = xb3.y & (xb3.x ^ wq[5]);
                    uint32_t m6 = xc1.y & (xc1.x ^ wq[6]);
                    uint32_t m7 = xc2.y & (xc2.x ^ wq[7]);
                    uint32_t m8 = xc3.y & (xc3.x ^ wq[8]);
                    uint32_t s0, c0, s1, c1, s2, c2, S, C2, S2, C4;
                    fa(m0, m1, m2, s0, c0);
                    fa(m3, m4, m5, s1, c1);
                    fa(m6, m7, m8, s2, c2);
                    fa(s0, s1, s2, S, C2);
                    fa(c0, c1, c2, S2, C4);
                    madacc1(acc1, __popc(S));
                    madacc2(acc1, __popc(C2));
                    madacc2(acc1, __popc(S2));
                    madacc4(acc1, __popc(C4));
                }
            }
            const int dot0 = madn2(acc0, sbase[r * W + w]);
            const int dot1 = madn2(acc1, sbase[r * W + w + 1]);
            const float t0 = fmaf((float)dot0, sc, sh);
            const float t1 = fmaf((float)dot1, sc, sh);
            if (STAGE == 1) {
                uint32_t sig0 = __ballot_sync(0xffffffffu, t0 > 0.f);
                uint32_t nz0 = __ballot_sync(0xffffffffu, t0 != 0.f);
                uint32_t sig1 = __ballot_sync(0xffffffffu, t1 > 0.f);
                uint32_t nz1 = __ballot_sync(0xffffffffu, t1 != 0.f);
                if (lane == 0) {
                    size_t gi = (((size_t)n * PD + (h0 + r + 1)) * PD + (w + 1)) * WORDS + wid;
                    g_p2[gi] = make_uint2(sig0, nz0);
                    g_p2[gi + WORDS] = make_uint2(sig1, nz1);
                }
            } else {
                stg[co * 57 + w] = t0;
                stg[co * 57 + w + 1] = t1;
            }
        }
        if (STAGE == 2) {
            __syncthreads();
            const int h = h0 + r;
            for (int i = tid; i < C * W; i += 256) {
                int c2 = i / W, w2 = i - c2 * W;
                size_t oi = (((size_t)n * C + c2) * H + h) * W + w2;
                float v = stg[c2 * 57 + w2] + xres[oi];
                out[oi] = fminf(1.f, fmaxf(-1.f, v));
            }
            __syncthreads();
        }
    }
}

extern "C" void kernel_launch(void* const* d_in, const int* in_sizes, int n_in,
                              void* d_out, int out_size) {
    (void)in_sizes; (void)n_in; (void)out_size;
    const float* x = (const float*)d_in[0];
    const float* w1 = (const float*)d_in[1];
    const float* g1 = (const float*)d_in[2];
    const float* b1 = (const float*)d_in[3];
    const float* m1 = (const float*)d_in[4];
    const float* v1 = (const float*)d_in[5];
    const float* w2 = (const float*)d_in[6];
    const float* g2 = (const float*)d_in[7];
    const float* b2 = (const float*)d_in[8];
    const float* m2 = (const float*)d_in[9];
    const float* v2 = (const float*)d_in[10];
    float* out = (float*)d_out;

    cudaFuncSetAttribute(k_bconv<1>, cudaFuncAttributeMaxDynamicSharedMemorySize, DYN1);
    cudaFuncSetAttribute(k_bconv<2>, cudaFuncAttributeMaxDynamicSharedMemorySize, DYN2);

    dim3 grid(H / TB, Nn);
    k_zero_border<<<Nn, 256>>>();
    k_pack_x<<<dim3(H, Nn), dim3(W, WORDS)>>>(x);
    k_pack_w<<<C, dim3(WORDS, 9)>>>(w1, 0);
    k_pack_w<<<C, dim3(WORDS, 9)>>>(w2, 1);
    k_prep_bn<<<1, C>>>(g1, b1, m1, v1, 0);
    k_bconv<1><<<grid, 256, DYN1>>>(x, out);
    k_prep_bn<<<1, C>>>(g2, b2, m2, v2, 1);
    k_bconv<2><<<grid, 256, DYN2>>>(x, out);
}

// round 17
// speedup vs baseline: 1.4874x; 1.0761x over previous
#include <cuda_runtime.h>
#include <stdint.h>

#define BN_EPS 1e-5f

namespace {
constexpr int Nn = 64, C = 256, H = 56, W = 56;
constexpr int PD = 58;             // padded dim
constexpr int WORDS = 8;           // channel words
constexpr int TB = 4;              // output rows per tile
constexpr int TR = TB + 2;         // tile rows (with halo)
constexpr int TRPD = TR * PD;      // 348
constexpr int NTILES = (H / TB) * Nn;             // 896 tiles per conv
constexpr int NBLOCKS = 296;                      // persistent blocks (148 SM x 2)
constexpr int TILE_U2 = WORDS * TRPD;             // 2784 uint2
constexpr int ZC_OFF = TILE_U2 * 8;               // 22272 B
constexpr int SB_OFF = ZC_OFF + TRPD * 4;         // 23664
constexpr int STG_OFF = SB_OFF + TB * W * 4;      // 24560
constexpr int DYN1 = STG_OFF;                     // conv1: 24560 B
constexpr int DYN2 = STG_OFF + C * 57 * 4;        // conv2: 82928 B
constexpr int NBORD = 4 * PD - 4;                 // 228 border pixels
}

// Packed (sign, nonzero) bitplanes, zero-padded borders. uint2 = (s, z).
__device__ uint2 g_p1[(size_t)Nn * PD * PD * WORDS];
__device__ uint2 g_p2[(size_t)Nn * PD * PD * WORDS];
__device__ uint32_t g_wb1[C * 72];   // [co][wd][tap]
__device__ uint32_t g_wb2[C * 72];
__device__ float g_sc1[C], g_sh1[C], g_sc2[C], g_sh2[C];
__device__ int g_ctr1, g_ctr2;       // persistent-scheduler tile counters

__device__ __forceinline__ void fa(uint32_t a, uint32_t b, uint32_t c,
                                   uint32_t& s, uint32_t& cy) {
    s = a ^ b ^ c;
    cy = (a & b) | (c & (a | b));
}
__device__ __forceinline__ void madacc1(int& a, int p) {  // a += p (fma pipe)
    asm("mad.lo.s32 %0, %1, 1, %0;" : "+r"(a) : "r"(p));
}
__device__ __forceinline__ void madacc2(int& a, int p) {  // a += 2*p (fma pipe)
    asm("mad.lo.s32 %0, %1, 2, %0;" : "+r"(a) : "r"(p));
}
__device__ __forceinline__ void madacc4(int& a, int p) {  // a += 4*p (fma pipe)
    asm("mad.lo.s32 %0, %1, 4, %0;" : "+r"(a) : "r"(p));
}
__device__ __forceinline__ int madn2(int acc, int d0) {   // d0 - 2*acc (fma pipe)
    int r;
    asm("mad.lo.s32 %0, %1, -2, %2;" : "=r"(r) : "r"(acc), "r"(d0));
    return r;
}

// Zero border pixels; also reset the persistent-scheduler counters (runs
// before the convs every graph replay -> deterministic).
__global__ void k_zero_border() {
    const int n = blockIdx.x, tid = threadIdx.x;
    if (n == 0 && tid == 0) { g_ctr1 = 0; g_ctr2 = 0; }
    for (int i = tid; i < NBORD * WORDS; i += 256) {
        int b = i >> 3, wd = i & 7;
        int ph, pw;
        if (b < PD) { ph = 0; pw = b; }
        else if (b < 2 * PD) { ph = PD - 1; pw = b - PD; }
        else if (b < 2 * PD + (PD - 2)) { ph = b - 2 * PD + 1; pw = 0; }
        else { ph = b - (2 * PD + PD - 2) + 1; pw = PD - 1; }
        size_t gi = (((size_t)n * PD + ph) * PD + pw) * WORDS + wd;
        g_p1[gi] = make_uint2(0u, 0u);
        g_p2[gi] = make_uint2(0u, 0u);
    }
}

// grid (H, N), block (W=56, WORDS=8)
__global__ void k_pack_x(const float* __restrict__ x) {
    const int h = blockIdx.x, n = blockIdx.y;
    const int w = threadIdx.x, wd = threadIdx.y;
    const float* xp = x + (((size_t)n * C + wd * 32) * H + h) * W + w;
    uint32_t s = 0, z = 0;
#pragma unroll
    for (int ci = 0; ci < 32; ci++) {
        float v = xp[(size_t)ci * (H * W)];
        s |= (v > 0.f ? 1u : 0u) << ci;
        z |= (v != 0.f ? 1u : 0u) << ci;
    }
    g_p1[(((size_t)n * PD + (h + 1)) * PD + (w + 1)) * WORDS + wd] = make_uint2(s, z);
}

// grid C, block (WORDS=8, 9): pack weights [co][wd][tap] + BN coeffs (fused).
__global__ void k_pack_w(const float* __restrict__ w, const float* __restrict__ g,
                         const float* __restrict__ b, const float* __restrict__ m,
                         const float* __restrict__ v, int which) {
    uint32_t* __restrict__ outw = which ? g_wb2 : g_wb1;
    const int co = blockIdx.x, wd = threadIdx.x, tap = threadIdx.y;
    uint32_t s = 0;
#pragma unroll
    for (int ci = 0; ci < 32; ci++)
        s |= (w[(((size_t)co * C) + wd * 32 + ci) * 9 + tap] > 0.f ? 1u : 0u) << ci;
    outw[co * 72 + wd * 9 + tap] = s;
    if (wd == 0 && tap == 0) {
        float sc = g[co] * rsqrtf(v[co] + BN_EPS);
        float sh = b[co] - m[co] * sc;
        if (which) { g_sc2[co] = sc; g_sh2[co] = sh; }
        else       { g_sc1[co] = sc; g_sh1[co] = sh; }
    }
}

// Co-stationary binary conv (R15 arithmetic, persistent scheduling):
// lane = output channel, weights register-resident (loaded once per block),
// per-wd 5-FA CSA + 4 POPC, w unrolled x2, LDS.128 window loads.
// 296 persistent blocks pull tiles off an atomic counter.
template <int STAGE>
__global__ __launch_bounds__(256, 2) void k_bconv(
    const float* __restrict__ xres, float* __restrict__ out) {
    const uint2* __restrict__ pin = (STAGE == 1) ? g_p1 : g_p2;
    const uint32_t* __restrict__ wb = (STAGE == 1) ? g_wb1 : g_wb2;

    extern __shared__ char sm[];
    uint2* tile = (uint2*)sm;                 // [wd][TR][58]
    int* zc = (int*)(sm + ZC_OFF);            // [TR*58]
    int* sbase = (int*)(sm + SB_OFF);         // [TB*56]
    float* stg = (float*)(sm + STG_OFF);      // conv2: [C][57]
    __shared__ int s_tile;

    const int tid = threadIdx.x;
    const int lane = tid & 31, wid = tid >> 5;
    const int co = wid * 32 + lane;

    // Per-block-lifetime state: weights + BN coefficients (loaded ONCE).
    uint32_t wk[72];
#pragma unroll
    for (int t = 0; t < 72; t++) wk[t] = __ldg(wb + co * 72 + t);
    const float sc = __ldg(((STAGE == 1) ? g_sc1 : g_sc2) + co);
    const float sh = __ldg(((STAGE == 1) ? g_sh1 : g_sh2) + co);
    int* ctr = (STAGE == 1) ? &g_ctr1 : &g_ctr2;

    for (;;) {
        if (tid == 0) s_tile = atomicAdd(ctr, 1);
        __syncthreads();                      // broadcast + prev-tile hazard
        const int tidx = s_tile;
        if (tidx >= NTILES) break;
        const int n = tidx / (H / TB);
        const int h0 = (tidx - n * (H / TB)) * TB;

        // Load tile as uint4 (pairs of uint2); layout [pix][wd], wd even-aligned.
        for (int i = tid; i < WORDS * TRPD / 2; i += 256) {
            int wd2 = i & 3, p = i >> 2;
            uint4 v = ((const uint4*)(pin + (((size_t)n * PD + h0) * PD) * WORDS))[p * 4 + wd2];
            uint2* dst0 = tile + (2 * wd2) * TRPD + p;
            dst0[0] = make_uint2(v.x, v.y);
            dst0[TRPD] = make_uint2(v.z, v.w);
        }
        __syncthreads();
        for (int p = tid; p < TRPD; p += 256) {
            int s = 0;
#pragma unroll
            for (int wd = 0; wd < 8; wd++) s += __popc(tile[wd * TRPD + p].y);
            zc[p] = s;
        }
        __syncthreads();
        for (int p = tid; p < TB * W; p += 256) {
            int r = p / W, w = p - r * W;
            int s = 0;
#pragma unroll
            for (int dh = 0; dh < 3; dh++)
#pragma unroll
                for (int dw = 0; dw < 3; dw++) s += zc[(r + dh) * PD + w + dw];
            sbase[p] = s;
        }
        __syncthreads();

        for (int r = 0; r < TB; r++) {
#pragma unroll 1
            for (int w = 0; w < W; w += 2) {
                int acc0 = 0, acc1 = 0;
#pragma unroll
                for (int wd = 0; wd < 8; wd++) {
                    const uint2* tp = tile + wd * TRPD + r * PD + w;
                    uint4 va0 = *(const uint4*)(tp);
                    uint4 va1 = *(const uint4*)(tp + 2);
                    uint4 vb0 = *(const uint4*)(tp + PD);
                    uint4 vb1 = *(const uint4*)(tp + PD + 2);
                    uint4 vc0 = *(const uint4*)(tp + 2 * PD);
                    uint4 vc1 = *(const uint4*)(tp + 2 * PD + 2);
                    uint2 xa0 = make_uint2(va0.x, va0.y), xa1 = make_uint2(va0.z, va0.w);
                    uint2 xa2 = make_uint2(va1.x, va1.y), xa3 = make_uint2(va1.z, va1.w);
                    uint2 xb0 = make_uint2(vb0.x, vb0.y), xb1 = make_uint2(vb0.z, vb0.w);
                    uint2 xb2 = make_uint2(vb1.x, vb1.y), xb3 = make_uint2(vb1.z, vb1.w);
                    uint2 xc0 = make_uint2(vc0.x, vc0.y), xc1 = make_uint2(vc0.z, vc0.w);
                    uint2 xc2 = make_uint2(vc1.x, vc1.y), xc3 = make_uint2(vc1.z, vc1.w);
                    const uint32_t* wq = wk + wd * 9;
                    // pixel w
                    {
                        uint32_t m0 = xa0.y & (xa0.x ^ wq[0]);
                        uint32_t m1 = xa1.y & (xa1.x ^ wq[1]);
                        uint32_t m2 = xa2.y & (xa2.x ^ wq[2]);
                        uint32_t m3 = xb0.y & (xb0.x ^ wq[3]);
                        uint32_t m4 = xb1.y & (xb1.x ^ wq[4]);
                        uint32_t m5 = xb2.y & (xb2.x ^ wq[5]);
                        uint32_t m6 = xc0.y & (xc0.x ^ wq[6]);
                        uint32_t m7 = xc1.y & (xc1.x ^ wq[7]);
                        uint32_t m8 = xc2.y & (xc2.x ^ wq[8]);
                        uint32_t s0, c0, s1, c1, s2, c2, S, C2, S2, C4;
                        fa(m0, m1, m2, s0, c0);
                        fa(m3, m4, m5, s1, c1);
                        fa(m6, m7, m8, s2, c2);
                        fa(s0, s1, s2, S, C2);
                        fa(c0, c1, c2, S2, C4);
                        madacc1(acc0, __popc(S));
                        madacc2(acc0, __popc(C2));
                        madacc2(acc0, __popc(S2));
                        madacc4(acc0, __popc(C4));
                    }
                    // pixel w+1
                    {
                        uint32_t m0 = xa1.y & (xa1.x ^ wq[0]);
                        uint32_t m1 = xa2.y & (xa2.x ^ wq[1]);
                        uint32_t m2 = xa3.y & (xa3.x ^ wq[2]);
                        uint32_t m3 = xb1.y & (xb1.x ^ wq[3]);
                        uint32_t m4 = xb2.y & (xb2.x ^ wq[4]);
                        uint32_t m5 = xb3.y & (xb3.x ^ wq[5]);
                        uint32_t m6 = xc1.y & (xc1.x ^ wq[6]);
                        uint32_t m7 = xc2.y & (xc2.x ^ wq[7]);
                        uint32_t m8 = xc3.y & (xc3.x ^ wq[8]);
                        uint32_t s0, c0, s1, c1, s2, c2, S, C2, S2, C4;
                        fa(m0, m1, m2, s0, c0);
                        fa(m3, m4, m5, s1, c1);
                        fa(m6, m7, m8, s2, c2);
                        fa(s0, s1, s2, S, C2);
                        fa(c0, c1, c2, S2, C4);
                        madacc1(acc1, __popc(S));
                        madacc2(acc1, __popc(C2));
                        madacc2(acc1, __popc(S2));
                        madacc4(acc1, __popc(C4));
                    }
                }
                const int dot0 = madn2(acc0, sbase[r * W + w]);
                const int dot1 = madn2(acc1, sbase[r * W + w + 1]);
                const float t0 = fmaf((float)dot0, sc, sh);
                const float t1 = fmaf((float)dot1, sc, sh);
                if (STAGE == 1) {
                    uint32_t sig0 = __ballot_sync(0xffffffffu, t0 > 0.f);
                    uint32_t nz0 = __ballot_sync(0xffffffffu, t0 != 0.f);
                    uint32_t sig1 = __ballot_sync(0xffffffffu, t1 > 0.f);
                    uint32_t nz1 = __ballot_sync(0xffffffffu, t1 != 0.f);
                    if (lane == 0) {
                        size_t gi = (((size_t)n * PD + (h0 + r + 1)) * PD + (w + 1)) * WORDS + wid;
                        g_p2[gi] = make_uint2(sig0, nz0);
                        g_p2[gi + WORDS] = make_uint2(sig1, nz1);
                    }
                } else {
                    stg[co * 57 + w] = t0;
                    stg[co * 57 + w + 1] = t1;
                }
            }
            if (STAGE == 2) {
                __syncthreads();
                const int h = h0 + r;
                for (int i = tid; i < C * W; i += 256) {
                    int c2 = i / W, w2 = i - c2 * W;
                    size_t oi = (((size_t)n * C + c2) * H + h) * W + w2;
                    float v = stg[c2 * 57 + w2] + xres[oi];
                    out[oi] = fminf(1.f, fmaxf(-1.f, v));
                }
                __syncthreads();
            }
        }
    }
}

extern "C" void kernel_launch(void* const* d_in, const int* in_sizes, int n_in,
                              void* d_out, int out_size) {
    (void)in_sizes; (void)n_in; (void)out_size;
    const float* x = (const float*)d_in[0];
    const float* w1 = (const float*)d_in[1];
    const float* g1 = (const float*)d_in[2];
    const float* b1 = (const float*)d_in[3];
    const float* m1 = (const float*)d_in[4];
    const float* v1 = (const float*)d_in[5];
    const float* w2 = (const float*)d_in[6];
    const float* g2 = (const float*)d_in[7];
    const float* b2 = (const float*)d_in[8];
    const float* m2 = (const float*)d_in[9];
    const float* v2 = (const float*)d_in[10];
    float* out = (float*)d_out;

    cudaFuncSetAttribute(k_bconv<1>, cudaFuncAttributeMaxDynamicSharedMemorySize, DYN1);
    cudaFuncSetAttribute(k_bconv<2>, cudaFuncAttributeMaxDynamicSharedMemorySize, DYN2);

    k_zero_border<<<Nn, 256>>>();
    k_pack_x<<<dim3(H, Nn), dim3(W, WORDS)>>>(x);
    k_pack_w<<<C, dim3(WORDS, 9)>>>(w1, g1, b1, m1, v1, 0);
    k_pack_w<<<C, dim3(WORDS, 9)>>>(w2, g2, b2, m2, v2, 1);
    k_bconv<1><<<NBLOCKS, 256, DYN1>>>(x, out);
    k_bconv<2><<<NBLOCKS, 256, DYN2>>>(x, out);
}